// round 5
// baseline (speedup 1.0000x reference)
#include <cuda_runtime.h>
#include <cstdint>

#define SEQ   2048
#define BATCH 32
#define IDIM  256
#define HDIM  256
#define G4    1024

// 268 MB scratch for precomputed input projections: Xg[t][b][g]
__device__ float g_xg[SEQ * BATCH * G4];

// ---------------------------------------------------------------------------
// Kernel 1 (unchanged control): Xg = x @ W_ih^T + b_ih + b_hh
// ---------------------------------------------------------------------------
#define BM 64
#define BN 64
#define BK 32

__global__ __launch_bounds__(256) void xproj_kernel(
    const float* __restrict__ x,
    const float* __restrict__ Wih,
    const float* __restrict__ bih,
    const float* __restrict__ bhh)
{
    __shared__ float As[BK][BM];
    __shared__ float Bs[BK][BN];

    const int tid  = threadIdx.x;
    const int mblk = blockIdx.x;
    const int nblk = blockIdx.y;

    const float* Arow = x   + (size_t)mblk * BM * IDIM;
    const float* Brow = Wih + (size_t)nblk * BN * IDIM;

    const int tx = tid & 15;
    const int ty = tid >> 4;

    float acc[4][4] = {};

    const int lr  = tid >> 2;
    const int lkq = (tid & 3) * 8;

    for (int k0 = 0; k0 < IDIM; k0 += BK) {
        {
            float4 v0 = *(const float4*)(Arow + lr * IDIM + k0 + lkq);
            float4 v1 = *(const float4*)(Arow + lr * IDIM + k0 + lkq + 4);
            As[lkq + 0][lr] = v0.x; As[lkq + 1][lr] = v0.y;
            As[lkq + 2][lr] = v0.z; As[lkq + 3][lr] = v0.w;
            As[lkq + 4][lr] = v1.x; As[lkq + 5][lr] = v1.y;
            As[lkq + 6][lr] = v1.z; As[lkq + 7][lr] = v1.w;

            float4 w0 = *(const float4*)(Brow + lr * IDIM + k0 + lkq);
            float4 w1 = *(const float4*)(Brow + lr * IDIM + k0 + lkq + 4);
            Bs[lkq + 0][lr] = w0.x; Bs[lkq + 1][lr] = w0.y;
            Bs[lkq + 2][lr] = w0.z; Bs[lkq + 3][lr] = w0.w;
            Bs[lkq + 4][lr] = w1.x; Bs[lkq + 5][lr] = w1.y;
            Bs[lkq + 6][lr] = w1.z; Bs[lkq + 7][lr] = w1.w;
        }
        __syncthreads();

        #pragma unroll
        for (int kk = 0; kk < BK; kk++) {
            float4 av = *(const float4*)&As[kk][ty * 4];
            float4 bv = *(const float4*)&Bs[kk][tx * 4];
            float a[4] = {av.x, av.y, av.z, av.w};
            float b[4] = {bv.x, bv.y, bv.z, bv.w};
            #pragma unroll
            for (int i = 0; i < 4; i++)
                #pragma unroll
                for (int jj = 0; jj < 4; jj++)
                    acc[i][jj] = fmaf(a[i], b[jj], acc[i][jj]);
        }
        __syncthreads();
    }

    const int mb = mblk * BM + ty * 4;
    const int nb = nblk * BN + tx * 4;
    float bias[4];
    #pragma unroll
    for (int jj = 0; jj < 4; jj++)
        bias[jj] = bih[nb + jj] + bhh[nb + jj];

    #pragma unroll
    for (int i = 0; i < 4; i++) {
        float4 v;
        v.x = acc[i][0] + bias[0];
        v.y = acc[i][1] + bias[1];
        v.z = acc[i][2] + bias[2];
        v.w = acc[i][3] + bias[3];
        *(float4*)&g_xg[(size_t)(mb + i) * G4 + nb] = v;
    }
}

// ---------------------------------------------------------------------------
// Kernel 2: warp-autonomous recurrence.
// 16 clusters x 8 CTAs; cluster owns 2 batches; CTA rank owns 32 hidden units.
// 512 threads. Lane map: kseg = lane>>3 (64-wide K segment), gl = (lane>>1)&3
// (gate), e = lane&1; warp w owns units {2w, 2w+1}. Each lane computes one
// gate-row x 2 batches over its K segment (weights in 32 u64 regs), reduces
// across ksegs with 2 bfly shuffles, activates its gate, gathers the 4 gates
// with 4 shuffles, updates c/h redundantly, and issues exactly ONE st.async
// (its unit's h for bb=(lane>>1)&1 to rank lane>>2). No __syncthreads in the
// loop; the per-buffer mbarrier phase is the only synchronization.
// ---------------------------------------------------------------------------
__device__ __forceinline__ void ffma2(uint64_t& acc, uint64_t a, uint64_t b) {
    asm("fma.rn.f32x2 %0, %1, %2, %0;" : "+l"(acc) : "l"(a), "l"(b));
}
__device__ __forceinline__ uint64_t fadd2(uint64_t a, uint64_t b) {
    uint64_t r;
    asm("add.rn.f32x2 %0, %1, %2;" : "=l"(r) : "l"(a), "l"(b));
    return r;
}
__device__ __forceinline__ float hsum2(uint64_t a) {
    uint32_t lo, hi;
    asm("mov.b64 {%0,%1}, %2;" : "=r"(lo), "=r"(hi) : "l"(a));
    return __uint_as_float(lo) + __uint_as_float(hi);
}
__device__ __forceinline__ void mbar_wait(uint32_t addr, unsigned par) {
    asm volatile(
        "{\n\t"
        ".reg .pred P;\n\t"
        "WAIT_%=:\n\t"
        "mbarrier.try_wait.parity.acquire.cta.shared::cta.b64 P, [%0], %1, 0x989680;\n\t"
        "@P bra DONE_%=;\n\t"
        "bra WAIT_%=;\n\t"
        "DONE_%=:\n\t"
        "}"
        :: "r"(addr), "r"(par) : "memory");
}

// h layout: [buf][bb][kseg][68] floats (64 used + 4 pad -> kseg chunks land on
// banks {0,4,8,12}(+16 for bb) => conflict-free 4-address broadcast LDS).
#define CH   68
#define BBST (4 * CH)            // 272 floats per bb
#define BUFST (2 * BBST)         // 544 floats per buf

__global__ void __cluster_dims__(8, 1, 1) __launch_bounds__(512, 1)
lstm_rec_kernel(const float* __restrict__ Whh,
                const float* __restrict__ h0,
                const float* __restrict__ c0,
                float* __restrict__ out)
{
    __shared__ float h_s[2 * BUFST];
    __shared__ alignas(8) unsigned long long mbar[2];

    const int tid  = threadIdx.x;
    const int lane = tid & 31;
    const int w    = tid >> 5;
    const int kseg = lane >> 3;
    const int gl   = (lane >> 1) & 3;
    const int e    = lane & 1;
    const int unit = 2 * w + e;            // 0..31 local hidden unit

    unsigned rank;
    asm("mov.u32 %0, %%cluster_ctarank;" : "=r"(rank));
    const int b0 = (blockIdx.x >> 3) * 2;
    const int R  = gl * 256 + (int)rank * 32 + unit;   // W_hh row / xg column

    // ---- weights: 64 floats packed into 32 u64 pairs ----
    uint64_t wp[32];
    {
        const float* W = Whh + (size_t)R * HDIM + kseg * 64;
        #pragma unroll
        for (int i = 0; i < 16; i++) {
            float4 v = *(const float4*)(W + 4 * i);
            asm("mov.b64 %0, {%1,%2};" : "=l"(wp[2*i+0]) : "f"(v.x), "f"(v.y));
            asm("mov.b64 %0, {%1,%2};" : "=l"(wp[2*i+1]) : "f"(v.z), "f"(v.w));
        }
    }

    // ---- init h_s buf0 with h0 (padded layout) ----
    for (int i = tid; i < 2 * HDIM; i += 512) {
        int bb = i >> 8, k = i & 255;
        h_s[bb * BBST + (k >> 6) * CH + (k & 63)] = h0[(size_t)(b0 + bb) * HDIM + k];
    }

    // ---- c state: every lane redundantly holds c for its unit, both bb ----
    float cb0 = c0[(size_t)(b0 + 0) * HDIM + (int)rank * 32 + unit];
    float cb1 = c0[(size_t)(b0 + 1) * HDIM + (int)rank * 32 + unit];
    float h_keep = 0.f;                     // last h for (unit, bbp)

    const uint32_t mb_addr = (uint32_t)__cvta_generic_to_shared(&mbar[0]);
    if (tid == 0) {
        asm volatile("mbarrier.init.shared.b64 [%0], %1;" :: "r"(mb_addr), "r"(1) : "memory");
        asm volatile("mbarrier.init.shared.b64 [%0], %1;" :: "r"(mb_addr + 8), "r"(1) : "memory");
        asm volatile("mbarrier.arrive.expect_tx.shared.b64 _, [%0], %1;" :: "r"(mb_addr), "r"(2048) : "memory");
        asm volatile("mbarrier.arrive.expect_tx.shared.b64 _, [%0], %1;" :: "r"(mb_addr + 8), "r"(2048) : "memory");
    }
    __syncthreads();
    asm volatile("barrier.cluster.arrive.aligned;" ::: "memory");
    asm volatile("barrier.cluster.wait.aligned;" ::: "memory");

    const uint32_t h_base = (uint32_t)__cvta_generic_to_shared(&h_s[0]);

    // store-duty constants: this lane stores (unit, bbp) to rank rdest
    const int bbp   = (lane >> 1) & 1;
    const int rdest = lane >> 2;
    const int kglob = (int)rank * 32 + unit;
    const uint32_t woff_base = (uint32_t)((bbp * BBST + (kglob >> 6) * CH + (kglob & 63)) * 4);

    auto step = [&](int t, int rd, bool dowait, unsigned par, bool dostore) {
        // xg prefetch (independent of h) — overlaps wait + k-loop
        const float* xp = g_xg + ((size_t)t * BATCH + b0) * G4 + R;
        const float xg0 = __ldg(xp);
        const float xg1 = __ldg(xp + G4);

        const uint32_t mb_rd = mb_addr + (uint32_t)rd * 8;
        if (dowait) {
            mbar_wait(mb_rd, par);
            if (tid == 0)
                asm volatile("mbarrier.arrive.expect_tx.shared.b64 _, [%0], %1;"
                             :: "r"(mb_rd), "r"(2048) : "memory");
        }

        // ---- k-loop: 64 K x 2 batches, packed f32x2 ----
        const uint32_t a0 = h_base + (uint32_t)(rd * BUFST + kseg * CH) * 4;
        const uint32_t a1 = a0 + BBST * 4;
        uint64_t acc0 = 0ull, acc1 = 0ull;
        #pragma unroll
        for (int i = 0; i < 64; i += 4) {
            uint64_t u01, u23, v01, v23;
            asm volatile("ld.shared.v2.u64 {%0,%1}, [%2];"
                         : "=l"(u01), "=l"(u23) : "r"(a0 + i * 4));
            asm volatile("ld.shared.v2.u64 {%0,%1}, [%2];"
                         : "=l"(v01), "=l"(v23) : "r"(a1 + i * 4));
            ffma2(acc0, wp[i / 2 + 0], u01);
            ffma2(acc1, wp[i / 2 + 0], v01);
            ffma2(acc0, wp[i / 2 + 1], u23);
            ffma2(acc1, wp[i / 2 + 1], v23);
        }

        // ---- kseg reduce: 2 bfly rounds (all lanes end with full sum) ----
        acc0 = fadd2(acc0, __shfl_xor_sync(0xffffffffu, acc0, 8));
        acc1 = fadd2(acc1, __shfl_xor_sync(0xffffffffu, acc1, 8));
        acc0 = fadd2(acc0, __shfl_xor_sync(0xffffffffu, acc0, 16));
        acc1 = fadd2(acc1, __shfl_xor_sync(0xffffffffu, acc1, 16));
        const float s0 = hsum2(acc0) + xg0;
        const float s1 = hsum2(acc1) + xg1;

        // ---- per-lane activation of its own gate (uniform path) ----
        // sigmoid(x) = 1/(1+e^-x); tanh(x) = 1 - 2/(1+e^{2x})
        const bool isg = (gl == 2);
        const float z0 = isg ? 2.f * s0 : -s0;
        const float z1 = isg ? 2.f * s1 : -s1;
        const float r0 = __fdividef(1.f, 1.f + __expf(z0));
        const float r1 = __fdividef(1.f, 1.f + __expf(z1));
        const float act0 = isg ? 1.f - 2.f * r0 : r0;
        const float act1 = isg ? 1.f - 2.f * r1 : r1;

        // ---- gather 4 gates for my unit (same kseg/e, vary gate bits) ----
        const int lb = lane & 25;     // keep kseg+e bits, clear gate bits
        const float gi0 = __shfl_sync(0xffffffffu, act0, lb | 0);
        const float gf0 = __shfl_sync(0xffffffffu, act0, lb | 2);
        const float gg0 = __shfl_sync(0xffffffffu, act0, lb | 4);
        const float go0 = __shfl_sync(0xffffffffu, act0, lb | 6);
        const float gi1 = __shfl_sync(0xffffffffu, act1, lb | 0);
        const float gf1 = __shfl_sync(0xffffffffu, act1, lb | 2);
        const float gg1 = __shfl_sync(0xffffffffu, act1, lb | 4);
        const float go1 = __shfl_sync(0xffffffffu, act1, lb | 6);

        cb0 = gf0 * cb0 + gi0 * gg0;
        cb1 = gf1 * cb1 + gi1 * gg1;
        const float th0 = 1.f - 2.f * __fdividef(1.f, 1.f + __expf(2.f * cb0));
        const float th1 = 1.f - 2.f * __fdividef(1.f, 1.f + __expf(2.f * cb1));
        const float hb0 = go0 * th0;
        const float hb1 = go1 * th1;

        const float hv = bbp ? hb1 : hb0;
        h_keep = hv;

        // ys output: lanes with rdest==0 cover all 4 (unit,bb) states of warp
        if (rdest == 0)
            out[((size_t)t * BATCH + b0 + bbp) * HDIM + kglob] = hv;

        // broadcast: one st.async per lane -> rank rdest
        if (dostore) {
            const uint32_t lh = h_base + (uint32_t)((rd ^ 1) * BUFST * 4) + woff_base;
            const uint32_t lm = mb_addr + (uint32_t)((rd ^ 1) * 8);
            uint32_t rh, rm;
            asm volatile("mapa.shared::cluster.u32 %0, %1, %2;"
                         : "=r"(rh) : "r"(lh), "r"(rdest));
            asm volatile("mapa.shared::cluster.u32 %0, %1, %2;"
                         : "=r"(rm) : "r"(lm), "r"(rdest));
            asm volatile(
                "st.async.shared::cluster.mbarrier::complete_tx::bytes.b32 [%0], %1, [%2];"
                :: "r"(rh), "f"(hv), "r"(rm) : "memory");
        }
    };

    unsigned par0 = 0, par1 = 0;
    step(SEQ - 1, 0, false, 0, true);
    for (int t = SEQ - 2; t >= 1; t -= 2) {
        step(t,     1, true, par1, true); par1 ^= 1;
        step(t - 1, 0, true, par0, true); par0 ^= 1;
    }
    step(0, 1, true, par1, false);

    if (rdest == 0) {
        float* hT = out + (size_t)SEQ * BATCH * HDIM;
        float* cT = hT + (size_t)BATCH * HDIM;
        hT[(size_t)(b0 + bbp) * HDIM + kglob] = h_keep;
        cT[(size_t)(b0 + bbp) * HDIM + kglob] = bbp ? cb1 : cb0;
    }
}

// ---------------------------------------------------------------------------
extern "C" void kernel_launch(void* const* d_in, const int* in_sizes, int n_in,
                              void* d_out, int out_size)
{
    (void)in_sizes; (void)n_in; (void)out_size;
    const float* x   = (const float*)d_in[0];
    const float* h0  = (const float*)d_in[1];
    const float* c0  = (const float*)d_in[2];
    const float* Wih = (const float*)d_in[3];
    const float* Whh = (const float*)d_in[4];
    const float* bih = (const float*)d_in[5];
    const float* bhh = (const float*)d_in[6];
    float* out = (float*)d_out;

    dim3 gridP(65536 / BM, G4 / BN);
    xproj_kernel<<<gridP, 256>>>(x, Wih, bih, bhh);

    lstm_rec_kernel<<<128, 512>>>(Whh, h0, c0, out);
}

// round 7
// speedup vs baseline: 1.0111x; 1.0111x over previous
#include <cuda_runtime.h>
#include <cstdint>

#define SEQ   2048
#define BATCH 32
#define IDIM  256
#define HDIM  256
#define G4    1024

// ---- dynamic smem layout (bytes) ----
// Wih2 : [128 k2][128 rows] float2      = 131072
// h_s  : [2 buf][2 bb][256] float       =   4096
// red_s: [4 kseg][2 bb][128] float      =   4096
// x2_s : [2 buf][2 bb][256] float       =   4096
// mbar : 2 x u64                        =     16
#define OFF_WIH 0
#define OFF_H   131072
#define OFF_RED (131072 + 4096)
#define OFF_X   (131072 + 8192)
#define OFF_MB  (131072 + 12288)
#define SMEM_TOT (131072 + 12288 + 16)

__device__ __forceinline__ void ffma2(uint64_t& acc, uint64_t a, uint64_t b) {
    asm("fma.rn.f32x2 %0, %1, %2, %0;" : "+l"(acc) : "l"(a), "l"(b));
}
__device__ __forceinline__ float hsum2(uint64_t a) {
    uint32_t lo, hi;
    asm("mov.b64 {%0,%1}, %2;" : "=r"(lo), "=r"(hi) : "l"(a));
    return __uint_as_float(lo) + __uint_as_float(hi);
}
__device__ __forceinline__ void mbar_wait(uint32_t addr, unsigned par) {
    asm volatile(
        "{\n\t"
        ".reg .pred P;\n\t"
        "WAIT_%=:\n\t"
        "mbarrier.try_wait.parity.acquire.cta.shared::cta.b64 P, [%0], %1, 0x989680;\n\t"
        "@P bra DONE_%=;\n\t"
        "bra WAIT_%=;\n\t"
        "DONE_%=:\n\t"
        "}"
        :: "r"(addr), "r"(par) : "memory");
}

// ---------------------------------------------------------------------------
// Fused reverse-LSTM: 16 clusters x 8 CTAs, cluster owns 2 batches, CTA rank
// owns 32 hidden units (128 gate rows). 512 threads: warp w -> kseg = w>>2
// (64-wide K segment), lr = (w&3)*32+lane (gate row). Per step:
//   [LDG prefetch x(t-1)] -> x-part matvec from smem W_ih slice (pre-wait,
//   fills the sync-latency window) -> mbarrier wait on h -> h-part k-loop
//   (weights in 32 u64 regs, FFMA2) -> red_s write + x2_s store -> one
//   __syncthreads -> 64 owner threads: reduce + activations + ys store +
//   st.async h broadcast to 8 ranks (hoisted mapa bases).
// Buffer parity: step for time t uses rd(t) = (t+1)&1; every step t>=1
// prefetches x[t-1] into buf rd^1 and broadcasts h into buf rd^1.
// ---------------------------------------------------------------------------
__global__ void __cluster_dims__(8, 1, 1) __launch_bounds__(512, 1)
lstm_fused_kernel(const float* __restrict__ x,
                  const float* __restrict__ h0,
                  const float* __restrict__ c0,
                  const float* __restrict__ Wih,
                  const float* __restrict__ Whh,
                  const float* __restrict__ bih,
                  const float* __restrict__ bhh,
                  float* __restrict__ out)
{
    extern __shared__ char smem_dyn[];
    float*    const wih_f  = (float*)(smem_dyn + OFF_WIH);
    uint64_t* const wih_u  = (uint64_t*)(smem_dyn + OFF_WIH);
    float*    const h_f    = (float*)(smem_dyn + OFF_H);
    float*    const red_f  = (float*)(smem_dyn + OFF_RED);
    float*    const x2_f   = (float*)(smem_dyn + OFF_X);
    uint64_t* const x2_u   = (uint64_t*)(smem_dyn + OFF_X);

    const int tid  = threadIdx.x;
    const int lane = tid & 31;
    const int w    = tid >> 5;
    const int kseg = w >> 2;                 // 0..3
    const int lr   = (w & 3) * 32 + lane;    // 0..127 local gate row

    unsigned rank;
    asm("mov.u32 %0, %%cluster_ctarank;" : "=r"(rank));
    const int b0 = (blockIdx.x >> 3) * 2;
    const int R  = ((lr >> 5) << 8) + (int)rank * 32 + (lr & 31);  // global gate row

    const uint32_t smem_base = (uint32_t)__cvta_generic_to_shared(smem_dyn);
    const uint32_t mb_addr   = smem_base + OFF_MB;

    // ---- W_hh slice into registers: 64 floats -> 32 u64 k-pairs ----
    uint64_t wp[32];
    {
        const float* W = Whh + (size_t)R * HDIM + kseg * 64;
        #pragma unroll
        for (int i = 0; i < 16; i++) {
            float4 v = *(const float4*)(W + 4 * i);
            asm("mov.b64 %0, {%1,%2};" : "=l"(wp[2*i+0]) : "f"(v.x), "f"(v.y));
            asm("mov.b64 %0, {%1,%2};" : "=l"(wp[2*i+1]) : "f"(v.z), "f"(v.w));
        }
    }

    // ---- W_ih slice into smem, transposed [k2][row] ----
    for (int idx = tid; idx < 128 * 128; idx += 512) {
        const int row = idx >> 7;            // 0..127
        const int k2  = idx & 127;           // 0..127
        const int gr  = ((row >> 5) << 8) + (int)rank * 32 + (row & 31);
        const float* src = Wih + (size_t)gr * IDIM + 2 * k2;
        wih_f[(k2 * 128 + row) * 2 + 0] = src[0];
        wih_f[(k2 * 128 + row) * 2 + 1] = src[1];
    }

    // ---- bias (packed into accumulator init for kseg 0) ----
    uint64_t bias_pk = 0ull;
    if (kseg == 0) {
        const float b = bih[R] + bhh[R];
        asm("mov.b64 %0, {%1,%2};" : "=l"(bias_pk) : "f"(b), "f"(0.f));
    }

    // ---- init h_s buf0 + x2_s buf0 (x[SEQ-1]) ----
    for (int i = tid; i < 2 * HDIM; i += 512)
        h_f[(i >> 8) * 256 + (i & 255)] = h0[(size_t)(b0 + (i >> 8)) * HDIM + (i & 255)];
    const int bbL = tid >> 8, kL = tid & 255;
    x2_f[bbL * 256 + kL] = x[((size_t)(SEQ - 1) * BATCH + b0 + bbL) * IDIM + kL];

    // ---- owners ----
    const int bb = w & 1;     // valid when tid < 64
    const int j  = lane;
    const int kglob = (int)rank * 32 + j;
    float c_reg = 0.f, h_last = 0.f;
    if (tid < 64)
        c_reg = c0[(size_t)(b0 + bb) * HDIM + kglob];

    if (tid == 0) {
        asm volatile("mbarrier.init.shared.b64 [%0], %1;" :: "r"(mb_addr), "r"(1) : "memory");
        asm volatile("mbarrier.init.shared.b64 [%0], %1;" :: "r"(mb_addr + 8), "r"(1) : "memory");
        asm volatile("mbarrier.arrive.expect_tx.shared.b64 _, [%0], %1;" :: "r"(mb_addr), "r"(2048) : "memory");
        asm volatile("mbarrier.arrive.expect_tx.shared.b64 _, [%0], %1;" :: "r"(mb_addr + 8), "r"(2048) : "memory");
    }
    // hoisted mapa: peer smem-window base per rank
    uint32_t pb[8];
    #pragma unroll
    for (int r = 0; r < 8; r++)
        asm("mapa.shared::cluster.u32 %0, %1, %2;" : "=r"(pb[r]) : "r"(smem_base), "r"(r));

    __syncthreads();
    asm volatile("barrier.cluster.arrive.aligned;" ::: "memory");
    asm volatile("barrier.cluster.wait.aligned;" ::: "memory");

    auto step = [&](int t, int rd, bool dowait, unsigned par, bool dostore, bool dopf) {
        // prefetch next x row element (consumed post-k-loop)
        float rx = 0.f;
        if (dopf)
            rx = x[((size_t)(t - 1) * BATCH + b0 + bbL) * IDIM + kL];

        // ---- x-part: pre-wait matvec from smem W_ih (k2 = kseg*32 + i) ----
        uint64_t acc0 = bias_pk, acc1 = bias_pk;
        {
            const uint64_t* wv = wih_u + (size_t)(kseg * 32) * 128 + lr;
            const uint64_t* x0 = x2_u + rd * 256 + kseg * 32;
            const uint64_t* x1 = x0 + 128;
            #pragma unroll
            for (int i = 0; i < 32; i++) {
                const uint64_t wpair = wv[i * 128];
                ffma2(acc0, wpair, x0[i]);
                ffma2(acc1, wpair, x1[i]);
            }
        }

        const uint32_t mb_rd = mb_addr + (uint32_t)rd * 8;
        if (dowait) {
            mbar_wait(mb_rd, par);
            if (tid == 0)
                asm volatile("mbarrier.arrive.expect_tx.shared.b64 _, [%0], %1;"
                             :: "r"(mb_rd), "r"(2048) : "memory");
        }

        // ---- h-part: 64 K x 2 batches, weights in regs ----
        const uint32_t a0 = smem_base + OFF_H + (uint32_t)(rd * 512 + kseg * 64) * 4;
        const uint32_t a1 = a0 + 1024;
        #pragma unroll
        for (int i = 0; i < 64; i += 4) {
            uint64_t u01, u23, v01, v23;
            asm volatile("ld.shared.v2.u64 {%0,%1}, [%2];"
                         : "=l"(u01), "=l"(u23) : "r"(a0 + i * 4));
            asm volatile("ld.shared.v2.u64 {%0,%1}, [%2];"
                         : "=l"(v01), "=l"(v23) : "r"(a1 + i * 4));
            ffma2(acc0, wp[i / 2 + 0], u01);
            ffma2(acc1, wp[i / 2 + 0], v01);
            ffma2(acc0, wp[i / 2 + 1], u23);
            ffma2(acc1, wp[i / 2 + 1], v23);
        }
        red_f[kseg * 256 + 0 * 128 + lr] = hsum2(acc0);
        red_f[kseg * 256 + 1 * 128 + lr] = hsum2(acc1);

        if (dopf)
            x2_f[(rd ^ 1) * 512 + bbL * 256 + kL] = rx;

        __syncthreads();   // red_s + x2_s visible; h_s[rd] reads complete

        // ---- owners: reduce + activations + state + broadcast ----
        if (tid < 64) {
            float s0 = 0.f, s1 = 0.f, s2 = 0.f, s3 = 0.f;
            #pragma unroll
            for (int ks = 0; ks < 4; ks++) {
                const float* rp = red_f + ks * 256 + bb * 128;
                s0 += rp[ 0 + j];
                s1 += rp[32 + j];
                s2 += rp[64 + j];
                s3 += rp[96 + j];
            }
            const float ig = __fdividef(1.f, 1.f + __expf(-s0));
            const float fg = __fdividef(1.f, 1.f + __expf(-s1));
            const float gt = 1.f - 2.f * __fdividef(1.f, 1.f + __expf(2.f * s2));
            const float og = __fdividef(1.f, 1.f + __expf(-s3));

            c_reg = fg * c_reg + ig * gt;
            const float h = og * (1.f - 2.f * __fdividef(1.f, 1.f + __expf(2.f * c_reg)));
            h_last = h;

            out[((size_t)t * BATCH + b0 + bb) * HDIM + kglob] = h;

            if (dostore) {
                const uint32_t hoff = (uint32_t)(OFF_H + ((rd ^ 1) * 512 + bb * 256 + kglob) * 4);
                const uint32_t moff = (uint32_t)(OFF_MB + (rd ^ 1) * 8);
                #pragma unroll
                for (int r = 0; r < 8; r++) {
                    asm volatile(
                        "st.async.shared::cluster.mbarrier::complete_tx::bytes.b32 [%0], %1, [%2];"
                        :: "r"(pb[r] + hoff), "f"(h), "r"(pb[r] + moff) : "memory");
                }
            }
        }
    };

    // rd(t) = (t+1)&1. Loop pairs (even t, odd t-1) down to (2, 1); peel t=0.
    unsigned par0 = 0, par1 = 0;
    step(SEQ - 1, 0, false, 0, true, true);            // t=2047, rd=0
    for (int t = SEQ - 2; t >= 2; t -= 2) {
        step(t,     1, true, par1, true, true);  par1 ^= 1;   // even t, rd=1
        step(t - 1, 0, true, par0, true, true);  par0 ^= 1;   // odd t-1 (>=1), rd=0
    }
    step(0, 1, true, par1, false, false);              // t=0, rd=1

    if (tid < 64) {
        float* hT = out + (size_t)SEQ * BATCH * HDIM;
        float* cT = hT + (size_t)BATCH * HDIM;
        hT[(size_t)(b0 + bb) * HDIM + kglob] = h_last;
        cT[(size_t)(b0 + bb) * HDIM + kglob] = c_reg;
    }
}

// ---------------------------------------------------------------------------
extern "C" void kernel_launch(void* const* d_in, const int* in_sizes, int n_in,
                              void* d_out, int out_size)
{
    (void)in_sizes; (void)n_in; (void)out_size;
    const float* x   = (const float*)d_in[0];
    const float* h0  = (const float*)d_in[1];
    const float* c0  = (const float*)d_in[2];
    const float* Wih = (const float*)d_in[3];
    const float* Whh = (const float*)d_in[4];
    const float* bih = (const float*)d_in[5];
    const float* bhh = (const float*)d_in[6];
    float* out = (float*)d_out;

    static bool attr_done = false;
    if (!attr_done) {
        cudaFuncSetAttribute(lstm_fused_kernel,
                             cudaFuncAttributeMaxDynamicSharedMemorySize, SMEM_TOT);
        attr_done = true;
    }

    lstm_fused_kernel<<<128, 512, SMEM_TOT>>>(x, h0, c0, Wih, Whh, bih, bhh, out);
}

// round 8
// speedup vs baseline: 1.3180x; 1.3035x over previous
#include <cuda_runtime.h>
#include <cstdint>

#define SEQ   2048
#define BATCH 32
#define IDIM  256
#define HDIM  256
#define G4    1024

// 268 MB scratch for precomputed input projections: Xg[t][b][g]
__device__ float g_xg[SEQ * BATCH * G4];

// ---------------------------------------------------------------------------
// Kernel 1 (unchanged control): Xg = x @ W_ih^T + b_ih + b_hh
// ---------------------------------------------------------------------------
#define BM 64
#define BN 64
#define BK 32

__global__ __launch_bounds__(256) void xproj_kernel(
    const float* __restrict__ x,
    const float* __restrict__ Wih,
    const float* __restrict__ bih,
    const float* __restrict__ bhh)
{
    __shared__ float As[BK][BM];
    __shared__ float Bs[BK][BN];

    const int tid  = threadIdx.x;
    const int mblk = blockIdx.x;
    const int nblk = blockIdx.y;

    const float* Arow = x   + (size_t)mblk * BM * IDIM;
    const float* Brow = Wih + (size_t)nblk * BN * IDIM;

    const int tx = tid & 15;
    const int ty = tid >> 4;

    float acc[4][4] = {};

    const int lr  = tid >> 2;
    const int lkq = (tid & 3) * 8;

    for (int k0 = 0; k0 < IDIM; k0 += BK) {
        {
            float4 v0 = *(const float4*)(Arow + lr * IDIM + k0 + lkq);
            float4 v1 = *(const float4*)(Arow + lr * IDIM + k0 + lkq + 4);
            As[lkq + 0][lr] = v0.x; As[lkq + 1][lr] = v0.y;
            As[lkq + 2][lr] = v0.z; As[lkq + 3][lr] = v0.w;
            As[lkq + 4][lr] = v1.x; As[lkq + 5][lr] = v1.y;
            As[lkq + 6][lr] = v1.z; As[lkq + 7][lr] = v1.w;

            float4 w0 = *(const float4*)(Brow + lr * IDIM + k0 + lkq);
            float4 w1 = *(const float4*)(Brow + lr * IDIM + k0 + lkq + 4);
            Bs[lkq + 0][lr] = w0.x; Bs[lkq + 1][lr] = w0.y;
            Bs[lkq + 2][lr] = w0.z; Bs[lkq + 3][lr] = w0.w;
            Bs[lkq + 4][lr] = w1.x; Bs[lkq + 5][lr] = w1.y;
            Bs[lkq + 6][lr] = w1.z; Bs[lkq + 7][lr] = w1.w;
        }
        __syncthreads();

        #pragma unroll
        for (int kk = 0; kk < BK; kk++) {
            float4 av = *(const float4*)&As[kk][ty * 4];
            float4 bv = *(const float4*)&Bs[kk][tx * 4];
            float a[4] = {av.x, av.y, av.z, av.w};
            float b[4] = {bv.x, bv.y, bv.z, bv.w};
            #pragma unroll
            for (int i = 0; i < 4; i++)
                #pragma unroll
                for (int jj = 0; jj < 4; jj++)
                    acc[i][jj] = fmaf(a[i], b[jj], acc[i][jj]);
        }
        __syncthreads();
    }

    const int mb = mblk * BM + ty * 4;
    const int nb = nblk * BN + tx * 4;
    float bias[4];
    #pragma unroll
    for (int jj = 0; jj < 4; jj++)
        bias[jj] = bih[nb + jj] + bhh[nb + jj];

    #pragma unroll
    for (int i = 0; i < 4; i++) {
        float4 v;
        v.x = acc[i][0] + bias[0];
        v.y = acc[i][1] + bias[1];
        v.z = acc[i][2] + bias[2];
        v.w = acc[i][3] + bias[3];
        *(float4*)&g_xg[(size_t)(mb + i) * G4 + nb] = v;
    }
}

// ---------------------------------------------------------------------------
// Kernel 2: R4 structure + bulk-copy broadcast (8 mbarrier tx/step vs 512).
// h layout: [buf][rankblk(8)][bb(2)][32] -> each CTA's slice is one
// contiguous 256 B region, bulk-copied to all 8 peers.
// ---------------------------------------------------------------------------
__device__ __forceinline__ void ffma2(uint64_t& acc, uint64_t a, uint64_t b) {
    asm("fma.rn.f32x2 %0, %1, %2, %0;" : "+l"(acc) : "l"(a), "l"(b));
}
__device__ __forceinline__ float hsum2(uint64_t a) {
    uint32_t lo, hi;
    asm("mov.b64 {%0,%1}, %2;" : "=r"(lo), "=r"(hi) : "l"(a));
    return __uint_as_float(lo) + __uint_as_float(hi);
}
__device__ __forceinline__ void mbar_wait(uint32_t addr, unsigned par) {
    asm volatile(
        "{\n\t"
        ".reg .pred P;\n\t"
        "WAIT_%=:\n\t"
        "mbarrier.try_wait.parity.acquire.cta.shared::cta.b64 P, [%0], %1, 0x989680;\n\t"
        "@P bra DONE_%=;\n\t"
        "bra WAIT_%=;\n\t"
        "DONE_%=:\n\t"
        "}"
        :: "r"(addr), "r"(par) : "memory");
}

__global__ void __cluster_dims__(8, 1, 1) __launch_bounds__(512, 1)
lstm_rec_kernel(const float* __restrict__ Whh,
                const float* __restrict__ h0,
                const float* __restrict__ c0,
                float* __restrict__ out)
{
    // h_s[buf][rankblk][bb][32]
    __shared__ float h_s[2][8][2][32];
    __shared__ float red_s[4][2][128];       // [kseg][bb][local row]
    __shared__ alignas(8) unsigned long long mbar[2];

    const int tid  = threadIdx.x;
    const int lane = tid & 31;
    const int w    = tid >> 5;
    const int kseg = w >> 2;                 // 0..3
    const int lr   = (w & 3) * 32 + lane;    // 0..127 local gate row

    unsigned rank;
    asm("mov.u32 %0, %%cluster_ctarank;" : "=r"(rank));
    const int b0 = (blockIdx.x >> 3) * 2;
    const int R  = ((lr >> 5) << 8) + (int)rank * 32 + (lr & 31);

    // ---- W_hh slice into registers: 64 floats -> 32 u64 k-pairs ----
    uint64_t wp[32];
    {
        const float* W = Whh + (size_t)R * HDIM + kseg * 64;
        #pragma unroll
        for (int i = 0; i < 16; i++) {
            float4 v = *(const float4*)(W + 4 * i);
            asm("mov.b64 %0, {%1,%2};" : "=l"(wp[2*i+0]) : "f"(v.x), "f"(v.y));
            asm("mov.b64 %0, {%1,%2};" : "=l"(wp[2*i+1]) : "f"(v.z), "f"(v.w));
        }
    }

    // ---- init h_s buf0 with h0 (new layout) ----
    for (int i = tid; i < 2 * HDIM; i += 512) {
        const int bb = i >> 8, k = i & 255;
        h_s[0][k >> 5][bb][k & 31] = h0[(size_t)(b0 + bb) * HDIM + k];
    }

    // ---- owners (tid < 64): (bb, j) state cell ----
    const int bb = w & 1;
    const int j  = lane;
    const int kglob = (int)rank * 32 + j;
    float c_reg = 0.f, h_last = 0.f;
    if (tid < 64)
        c_reg = c0[(size_t)(b0 + bb) * HDIM + kglob];

    const uint32_t h_base  = (uint32_t)__cvta_generic_to_shared(&h_s[0][0][0][0]);
    const uint32_t mb_addr = (uint32_t)__cvta_generic_to_shared(&mbar[0]);
    const uint32_t mb_delta = mb_addr - h_base;

    if (tid == 0) {
        asm volatile("mbarrier.init.shared.b64 [%0], %1;" :: "r"(mb_addr), "r"(1) : "memory");
        asm volatile("mbarrier.init.shared.b64 [%0], %1;" :: "r"(mb_addr + 8), "r"(1) : "memory");
        asm volatile("mbarrier.arrive.expect_tx.shared.b64 _, [%0], %1;" :: "r"(mb_addr), "r"(2048) : "memory");
        asm volatile("mbarrier.arrive.expect_tx.shared.b64 _, [%0], %1;" :: "r"(mb_addr + 8), "r"(2048) : "memory");
    }
    // hoisted mapa of h_base per rank (mbar derived via constant delta)
    uint32_t ph[8];
    #pragma unroll
    for (int r = 0; r < 8; r++)
        asm("mapa.shared::cluster.u32 %0, %1, %2;" : "=r"(ph[r]) : "r"(h_base), "r"(r));

    __syncthreads();
    asm volatile("barrier.cluster.arrive.aligned;" ::: "memory");
    asm volatile("barrier.cluster.wait.aligned;" ::: "memory");

    auto step = [&](int t, int rd, bool dowait, unsigned par, bool dostore) {
        // xg prefetch (hidden under wait + k-loop)
        float xg0 = 0.f, xg1 = 0.f, xg2 = 0.f, xg3 = 0.f;
        if (tid < 64) {
            const float* xp = g_xg + ((size_t)t * BATCH + b0 + bb) * G4 + kglob;
            xg0 = __ldg(xp);
            xg1 = __ldg(xp + 256);
            xg2 = __ldg(xp + 512);
            xg3 = __ldg(xp + 768);
        }

        const uint32_t mb_rd = mb_addr + (uint32_t)rd * 8;
        if (dowait) {
            mbar_wait(mb_rd, par);
            if (tid == 0)
                asm volatile("mbarrier.arrive.expect_tx.shared.b64 _, [%0], %1;"
                             :: "r"(mb_rd), "r"(2048) : "memory");
        }

        // ---- k-loop: 2 chunks of 32 K x 2 batches, weights in regs ----
        // chunk c (= 2*kseg + half) base: h_base + rd*2048 + c*256 + bb*128
        const uint32_t c00 = h_base + (uint32_t)(rd * 2048 + kseg * 512);
        const uint32_t c01 = c00 + 128;
        const uint32_t c10 = c00 + 256;
        const uint32_t c11 = c10 + 128;
        uint64_t acc0 = 0ull, acc1 = 0ull;
        #pragma unroll
        for (int i = 0; i < 32; i += 4) {
            uint64_t u01, u23, v01, v23;
            asm volatile("ld.shared.v2.u64 {%0,%1}, [%2];"
                         : "=l"(u01), "=l"(u23) : "r"(c00 + i * 4));
            asm volatile("ld.shared.v2.u64 {%0,%1}, [%2];"
                         : "=l"(v01), "=l"(v23) : "r"(c01 + i * 4));
            ffma2(acc0, wp[i / 2 + 0], u01);
            ffma2(acc1, wp[i / 2 + 0], v01);
            ffma2(acc0, wp[i / 2 + 1], u23);
            ffma2(acc1, wp[i / 2 + 1], v23);
        }
        #pragma unroll
        for (int i = 0; i < 32; i += 4) {
            uint64_t u01, u23, v01, v23;
            asm volatile("ld.shared.v2.u64 {%0,%1}, [%2];"
                         : "=l"(u01), "=l"(u23) : "r"(c10 + i * 4));
            asm volatile("ld.shared.v2.u64 {%0,%1}, [%2];"
                         : "=l"(v01), "=l"(v23) : "r"(c11 + i * 4));
            ffma2(acc0, wp[16 + i / 2 + 0], u01);
            ffma2(acc1, wp[16 + i / 2 + 0], v01);
            ffma2(acc0, wp[16 + i / 2 + 1], u23);
            ffma2(acc1, wp[16 + i / 2 + 1], v23);
        }
        red_s[kseg][0][lr] = hsum2(acc0);
        red_s[kseg][1][lr] = hsum2(acc1);
        __syncthreads();

        // ---- owners: reduce + activations + state + bulk broadcast ----
        if (tid < 64) {
            float s0 = xg0, s1 = xg1, s2 = xg2, s3 = xg3;
            #pragma unroll
            for (int ks = 0; ks < 4; ks++) {
                s0 += red_s[ks][bb][ 0 + j];
                s1 += red_s[ks][bb][32 + j];
                s2 += red_s[ks][bb][64 + j];
                s3 += red_s[ks][bb][96 + j];
            }
            const float ig = __fdividef(1.f, 1.f + __expf(-s0));
            const float fg = __fdividef(1.f, 1.f + __expf(-s1));
            const float gt = 1.f - 2.f * __fdividef(1.f, 1.f + __expf(2.f * s2));
            const float og = __fdividef(1.f, 1.f + __expf(-s3));

            c_reg = fg * c_reg + ig * gt;
            const float h = og * (1.f - 2.f * __fdividef(1.f, 1.f + __expf(2.f * c_reg)));
            h_last = h;

            out[((size_t)t * BATCH + b0 + bb) * HDIM + kglob] = h;

            if (dostore) {
                const int wr = rd ^ 1;
                // stage own slice locally: h_s[wr][rank][bb][j]
                h_s[wr][rank][bb][j] = h;
                // owner barrier: drain the 64 STS
                asm volatile("bar.sync 1, 64;" ::: "memory");
                if (tid == 0) {
                    asm volatile("fence.proxy.async.shared::cta;" ::: "memory");
                    const uint32_t soff = (uint32_t)(wr * 2048 + (int)rank * 256);
                    const uint32_t src  = h_base + soff;
                    const uint32_t mo   = mb_delta + (uint32_t)wr * 8;
                    #pragma unroll
                    for (int r = 0; r < 8; r++) {
                        asm volatile(
                            "cp.async.bulk.shared::cluster.shared::cta.mbarrier::complete_tx::bytes "
                            "[%0], [%1], %2, [%3];"
                            :: "r"(ph[r] + soff), "r"(src), "r"(256), "r"(ph[r] + mo)
                            : "memory");
                    }
                }
            }
        }
    };

    // rd(t) = (t+1)&1. Loop pairs (even t, odd t-1) down to (2, 1); peel t=0.
    unsigned par0 = 0, par1 = 0;
    step(SEQ - 1, 0, false, 0, true);                   // t=2047, rd=0
    for (int t = SEQ - 2; t >= 2; t -= 2) {
        step(t,     1, true, par1, true);  par1 ^= 1;   // even t, rd=1
        step(t - 1, 0, true, par0, true);  par0 ^= 1;   // odd t-1, rd=0
    }
    step(0, 1, true, par1, false);                      // t=0, rd=1

    if (tid < 64) {
        float* hT = out + (size_t)SEQ * BATCH * HDIM;
        float* cT = hT + (size_t)BATCH * HDIM;
        hT[(size_t)(b0 + bb) * HDIM + kglob] = h_last;
        cT[(size_t)(b0 + bb) * HDIM + kglob] = c_reg;
    }
}

// ---------------------------------------------------------------------------
extern "C" void kernel_launch(void* const* d_in, const int* in_sizes, int n_in,
                              void* d_out, int out_size)
{
    (void)in_sizes; (void)n_in; (void)out_size;
    const float* x   = (const float*)d_in[0];
    const float* h0  = (const float*)d_in[1];
    const float* c0  = (const float*)d_in[2];
    const float* Wih = (const float*)d_in[3];
    const float* Whh = (const float*)d_in[4];
    const float* bih = (const float*)d_in[5];
    const float* bhh = (const float*)d_in[6];
    float* out = (float*)d_out;

    dim3 gridP(65536 / BM, G4 / BN);   // (1024, 16)
    xproj_kernel<<<gridP, 256>>>(x, Wih, bih, bhh);

    lstm_rec_kernel<<<128, 512>>>(Whh, h0, c0, out);
}

// round 9
// speedup vs baseline: 1.4907x; 1.1310x over previous
#include <cuda_runtime.h>
#include <cstdint>

#define SEQ   2048
#define BATCH 32
#define IDIM  256
#define HDIM  256
#define G4    1024

// 268 MB scratch for precomputed input projections: Xg[t][b][g]
__device__ float g_xg[SEQ * BATCH * G4];

// ---------------------------------------------------------------------------
// Kernel 1 (unchanged control): Xg = x @ W_ih^T + b_ih + b_hh
// ---------------------------------------------------------------------------
#define BM 64
#define BN 64
#define BK 32

__global__ __launch_bounds__(256) void xproj_kernel(
    const float* __restrict__ x,
    const float* __restrict__ Wih,
    const float* __restrict__ bih,
    const float* __restrict__ bhh)
{
    __shared__ float As[BK][BM];
    __shared__ float Bs[BK][BN];

    const int tid  = threadIdx.x;
    const int mblk = blockIdx.x;
    const int nblk = blockIdx.y;

    const float* Arow = x   + (size_t)mblk * BM * IDIM;
    const float* Brow = Wih + (size_t)nblk * BN * IDIM;

    const int tx = tid & 15;
    const int ty = tid >> 4;

    float acc[4][4] = {};

    const int lr  = tid >> 2;
    const int lkq = (tid & 3) * 8;

    for (int k0 = 0; k0 < IDIM; k0 += BK) {
        {
            float4 v0 = *(const float4*)(Arow + lr * IDIM + k0 + lkq);
            float4 v1 = *(const float4*)(Arow + lr * IDIM + k0 + lkq + 4);
            As[lkq + 0][lr] = v0.x; As[lkq + 1][lr] = v0.y;
            As[lkq + 2][lr] = v0.z; As[lkq + 3][lr] = v0.w;
            As[lkq + 4][lr] = v1.x; As[lkq + 5][lr] = v1.y;
            As[lkq + 6][lr] = v1.z; As[lkq + 7][lr] = v1.w;

            float4 w0 = *(const float4*)(Brow + lr * IDIM + k0 + lkq);
            float4 w1 = *(const float4*)(Brow + lr * IDIM + k0 + lkq + 4);
            Bs[lkq + 0][lr] = w0.x; Bs[lkq + 1][lr] = w0.y;
            Bs[lkq + 2][lr] = w0.z; Bs[lkq + 3][lr] = w0.w;
            Bs[lkq + 4][lr] = w1.x; Bs[lkq + 5][lr] = w1.y;
            Bs[lkq + 6][lr] = w1.z; Bs[lkq + 7][lr] = w1.w;
        }
        __syncthreads();

        #pragma unroll
        for (int kk = 0; kk < BK; kk++) {
            float4 av = *(const float4*)&As[kk][ty * 4];
            float4 bv = *(const float4*)&Bs[kk][tx * 4];
            float a[4] = {av.x, av.y, av.z, av.w};
            float b[4] = {bv.x, bv.y, bv.z, bv.w};
            #pragma unroll
            for (int i = 0; i < 4; i++)
                #pragma unroll
                for (int jj = 0; jj < 4; jj++)
                    acc[i][jj] = fmaf(a[i], b[jj], acc[i][jj]);
        }
        __syncthreads();
    }

    const int mb = mblk * BM + ty * 4;
    const int nb = nblk * BN + tx * 4;
    float bias[4];
    #pragma unroll
    for (int jj = 0; jj < 4; jj++)
        bias[jj] = bih[nb + jj] + bhh[nb + jj];

    #pragma unroll
    for (int i = 0; i < 4; i++) {
        float4 v;
        v.x = acc[i][0] + bias[0];
        v.y = acc[i][1] + bias[1];
        v.z = acc[i][2] + bias[2];
        v.w = acc[i][3] + bias[3];
        *(float4*)&g_xg[(size_t)(mb + i) * G4 + nb] = v;
    }
}

// ---------------------------------------------------------------------------
// Kernel 2: R4 recurrence + split barrier + own-rank STS shortcut.
// 16 clusters x 8 CTAs; cluster owns 2 batches; CTA rank owns 32 hidden
// units (128 gate rows). 512 threads: warp w -> kseg = w>>2, lr = (w&3)*32+lane.
// Per step: [owner xg LDG] -> mbar wait -> k-loop (weights in 32 u64 regs,
// FFMA2, broadcast LDS) -> red_s[rd] write -> non-owners: bar.arrive & next
// step; owners: bar.sync -> reduce + activations -> STS own h locally +
// st.async to 7 remote ranks (expect_tx 1792) -> STG ys.
// ---------------------------------------------------------------------------
__device__ __forceinline__ void ffma2(uint64_t& acc, uint64_t a, uint64_t b) {
    asm("fma.rn.f32x2 %0, %1, %2, %0;" : "+l"(acc) : "l"(a), "l"(b));
}
__device__ __forceinline__ float hsum2(uint64_t a) {
    uint32_t lo, hi;
    asm("mov.b64 {%0,%1}, %2;" : "=r"(lo), "=r"(hi) : "l"(a));
    return __uint_as_float(lo) + __uint_as_float(hi);
}
__device__ __forceinline__ void mbar_wait(uint32_t addr, unsigned par) {
    asm volatile(
        "{\n\t"
        ".reg .pred P;\n\t"
        "WAIT_%=:\n\t"
        "mbarrier.try_wait.parity.acquire.cta.shared::cta.b64 P, [%0], %1, 0x989680;\n\t"
        "@P bra DONE_%=;\n\t"
        "bra WAIT_%=;\n\t"
        "DONE_%=:\n\t"
        "}"
        :: "r"(addr), "r"(par) : "memory");
}

#define TX_PER_BUF 1792   // 7 remote ranks x 64 floats x 4 B

__global__ void __cluster_dims__(8, 1, 1) __launch_bounds__(512, 1)
lstm_rec_kernel(const float* __restrict__ Whh,
                const float* __restrict__ h0,
                const float* __restrict__ c0,
                float* __restrict__ out)
{
    __shared__ float h_s[2][2][HDIM];        // [buf][local batch][k]
    __shared__ float red_s[2][4][2][128];    // [rd][kseg][bb][local row]
    __shared__ alignas(8) unsigned long long mbar[2];

    const int tid  = threadIdx.x;
    const int lane = tid & 31;
    const int w    = tid >> 5;
    const int kseg = w >> 2;
    const int lr   = (w & 3) * 32 + lane;

    unsigned rank;
    asm("mov.u32 %0, %%cluster_ctarank;" : "=r"(rank));
    const int b0 = (blockIdx.x >> 3) * 2;
    const int R  = ((lr >> 5) << 8) + (int)rank * 32 + (lr & 31);

    // ---- W_hh slice into registers: 64 floats -> 32 u64 k-pairs ----
    uint64_t wp[32];
    {
        const float* W = Whh + (size_t)R * HDIM + kseg * 64;
        #pragma unroll
        for (int i = 0; i < 16; i++) {
            float4 v = *(const float4*)(W + 4 * i);
            asm("mov.b64 %0, {%1,%2};" : "=l"(wp[2*i+0]) : "f"(v.x), "f"(v.y));
            asm("mov.b64 %0, {%1,%2};" : "=l"(wp[2*i+1]) : "f"(v.z), "f"(v.w));
        }
    }

    // ---- init h_s buf0 with h0 ----
    for (int i = tid; i < 2 * HDIM; i += 512)
        h_s[0][i >> 8][i & 255] = h0[(size_t)(b0 + (i >> 8)) * HDIM + (i & 255)];

    // ---- owners (tid < 64): (bb, j) state cell ----
    const int bb = w & 1;
    const int j  = lane;
    const int kglob = (int)rank * 32 + j;
    float c_reg = 0.f, h_last = 0.f;
    if (tid < 64)
        c_reg = c0[(size_t)(b0 + bb) * HDIM + kglob];

    const uint32_t h_base  = (uint32_t)__cvta_generic_to_shared(&h_s[0][0][0]);
    const uint32_t mb_addr = (uint32_t)__cvta_generic_to_shared(&mbar[0]);
    const uint32_t mb_delta = mb_addr - h_base;

    if (tid == 0) {
        asm volatile("mbarrier.init.shared.b64 [%0], %1;" :: "r"(mb_addr), "r"(1) : "memory");
        asm volatile("mbarrier.init.shared.b64 [%0], %1;" :: "r"(mb_addr + 8), "r"(1) : "memory");
        asm volatile("mbarrier.arrive.expect_tx.shared.b64 _, [%0], %1;" :: "r"(mb_addr), "r"(TX_PER_BUF) : "memory");
        asm volatile("mbarrier.arrive.expect_tx.shared.b64 _, [%0], %1;" :: "r"(mb_addr + 8), "r"(TX_PER_BUF) : "memory");
    }
    // hoisted mapa of h_base per rank
    uint32_t ph[8];
    #pragma unroll
    for (int r = 0; r < 8; r++)
        asm("mapa.shared::cluster.u32 %0, %1, %2;" : "=r"(ph[r]) : "r"(h_base), "r"(r));

    __syncthreads();
    asm volatile("barrier.cluster.arrive.aligned;" ::: "memory");
    asm volatile("barrier.cluster.wait.aligned;" ::: "memory");

    auto step = [&](int t, int rd, bool dowait, unsigned par, bool dostore) {
        // xg prefetch (hidden under wait + k-loop)
        float xg0 = 0.f, xg1 = 0.f, xg2 = 0.f, xg3 = 0.f;
        if (tid < 64) {
            const float* xp = g_xg + ((size_t)t * BATCH + b0 + bb) * G4 + kglob;
            xg0 = __ldg(xp);
            xg1 = __ldg(xp + 256);
            xg2 = __ldg(xp + 512);
            xg3 = __ldg(xp + 768);
        }

        const uint32_t mb_rd = mb_addr + (uint32_t)rd * 8;
        if (dowait) {
            mbar_wait(mb_rd, par);
            if (tid == 0)
                asm volatile("mbarrier.arrive.expect_tx.shared.b64 _, [%0], %1;"
                             :: "r"(mb_rd), "r"(TX_PER_BUF) : "memory");
        }

        // ---- k-loop: 64 K x 2 batches, weights in regs, broadcast LDS ----
        const uint32_t a0 = h_base + (uint32_t)(rd * 512 + kseg * 64) * 4;
        const uint32_t a1 = a0 + 1024;
        uint64_t acc0 = 0ull, acc1 = 0ull;
        #pragma unroll
        for (int i = 0; i < 64; i += 4) {
            uint64_t u01, u23, v01, v23;
            asm volatile("ld.shared.v2.u64 {%0,%1}, [%2];"
                         : "=l"(u01), "=l"(u23) : "r"(a0 + i * 4));
            asm volatile("ld.shared.v2.u64 {%0,%1}, [%2];"
                         : "=l"(v01), "=l"(v23) : "r"(a1 + i * 4));
            ffma2(acc0, wp[i / 2 + 0], u01);
            ffma2(acc1, wp[i / 2 + 0], v01);
            ffma2(acc0, wp[i / 2 + 1], u23);
            ffma2(acc1, wp[i / 2 + 1], v23);
        }
        red_s[rd][kseg][0][lr] = hsum2(acc0);
        red_s[rd][kseg][1][lr] = hsum2(acc1);

        if (tid >= 64) {
            // non-owners: post results and immediately move to next step
            asm volatile("bar.arrive 1, 512;" ::: "memory");
            return;
        }

        // owners: wait for all 16 warps' red_s
        asm volatile("bar.sync 1, 512;" ::: "memory");

        float s0 = xg0, s1 = xg1, s2 = xg2, s3 = xg3;
        #pragma unroll
        for (int ks = 0; ks < 4; ks++) {
            s0 += red_s[rd][ks][bb][ 0 + j];
            s1 += red_s[rd][ks][bb][32 + j];
            s2 += red_s[rd][ks][bb][64 + j];
            s3 += red_s[rd][ks][bb][96 + j];
        }
        const float ig = __fdividef(1.f, 1.f + __expf(-s0));
        const float fg = __fdividef(1.f, 1.f + __expf(-s1));
        const float gt = 1.f - 2.f * __fdividef(1.f, 1.f + __expf(2.f * s2));
        const float og = __fdividef(1.f, 1.f + __expf(-s3));

        c_reg = fg * c_reg + ig * gt;
        const float h = og * (1.f - 2.f * __fdividef(1.f, 1.f + __expf(2.f * c_reg)));
        h_last = h;

        if (dostore) {
            const int wr = rd ^ 1;
            const uint32_t hoff = (uint32_t)(((wr * 2 + bb) * 256 + kglob) * 4);
            const uint32_t moff = mb_delta + (uint32_t)wr * 8;
            // own rank: plain local STS (visible long before phase flip)
            h_s[wr][bb][kglob] = h;
            // remote ranks: st.async with tx accounting
            #pragma unroll
            for (int r = 0; r < 8; r++) {
                if (r != (int)rank) {
                    asm volatile(
                        "st.async.shared::cluster.mbarrier::complete_tx::bytes.b32 [%0], %1, [%2];"
                        :: "r"(ph[r] + hoff), "f"(h), "r"(ph[r] + moff) : "memory");
                }
            }
        }

        out[((size_t)t * BATCH + b0 + bb) * HDIM + kglob] = h;
    };

    // rd(t) = (t+1)&1. Loop pairs (even t, odd t-1) down to (2, 1); peel t=0.
    unsigned par0 = 0, par1 = 0;
    step(SEQ - 1, 0, false, 0, true);                   // t=2047, rd=0
    for (int t = SEQ - 2; t >= 2; t -= 2) {
        step(t,     1, true, par1, true);  par1 ^= 1;   // even t, rd=1
        step(t - 1, 0, true, par0, true);  par0 ^= 1;   // odd t-1, rd=0
    }
    step(0, 1, true, par1, false);                      // t=0, rd=1

    if (tid < 64) {
        float* hT = out + (size_t)SEQ * BATCH * HDIM;
        float* cT = hT + (size_t)BATCH * HDIM;
        hT[(size_t)(b0 + bb) * HDIM + kglob] = h_last;
        cT[(size_t)(b0 + bb) * HDIM + kglob] = c_reg;
    }
}

// ---------------------------------------------------------------------------
extern "C" void kernel_launch(void* const* d_in, const int* in_sizes, int n_in,
                              void* d_out, int out_size)
{
    (void)in_sizes; (void)n_in; (void)out_size;
    const float* x   = (const float*)d_in[0];
    const float* h0  = (const float*)d_in[1];
    const float* c0  = (const float*)d_in[2];
    const float* Wih = (const float*)d_in[3];
    const float* Whh = (const float*)d_in[4];
    const float* bih = (const float*)d_in[5];
    const float* bhh = (const float*)d_in[6];
    float* out = (float*)d_out;

    dim3 gridP(65536 / BM, G4 / BN);   // (1024, 16)
    xproj_kernel<<<gridP, 256>>>(x, Wih, bih, bhh);

    lstm_rec_kernel<<<128, 512>>>(Whh, h0, c0, out);
}